// round 8
// baseline (speedup 1.0000x reference)
#include <cuda_runtime.h>
#include <cuda_bf16.h>
#include <cstdint>

// ---------------------------------------------------------------------------
// Problem constants
// ---------------------------------------------------------------------------
#define B_    32
#define N_    512
#define OBJ   2048
#define QD    1024
#define CD    3072
#define MTOT  16384
#define STOT  ((size_t)B_ * N_ * N_)

// ---------------------------------------------------------------------------
// Device scratch (static; no runtime allocation)
// ---------------------------------------------------------------------------
__device__ __align__(16) __nv_bfloat16 g_W1hi[(size_t)QD * OBJ];
__device__ __align__(16) float         g_W1q [(size_t)QD * QD];
__device__ __align__(16) __nv_bfloat16 g_W2hi[(size_t)QD * QD];
__device__ __align__(16) __nv_bfloat16 g_nhi [(size_t)MTOT * OBJ];
__device__ __align__(16) __nv_bfloat16 g_nlo [(size_t)MTOT * OBJ];
__device__ __align__(16) __nv_bfloat16 g_h1hi[(size_t)MTOT * QD];
__device__ __align__(16) __nv_bfloat16 g_h1lo[(size_t)MTOT * QD];
__device__ __align__(16) __nv_bfloat16 g_h2hi[(size_t)MTOT * QD];
__device__ __align__(16) __nv_bfloat16 g_h2lo[(size_t)MTOT * QD];
__device__ __align__(16) float g_S[STOT];
__device__ __align__(16) float g_qterm[B_ * QD];
__device__ unsigned int g_odd_or;

// ---------------------------------------------------------------------------
// helpers
// ---------------------------------------------------------------------------
__device__ __forceinline__ uint32_t smem_u32(const void* p) {
    uint32_t a;
    asm("{ .reg .u64 t; cvta.to.shared.u64 t, %1; cvt.u32.u64 %0, t; }" : "=r"(a) : "l"(p));
    return a;
}
__device__ __forceinline__ void cp16(uint32_t dst, const void* src) {
    asm volatile("cp.async.ca.shared.global [%0], [%1], 16;" :: "r"(dst), "l"(src) : "memory");
}
__device__ __forceinline__ void cp_commit() {
    asm volatile("cp.async.commit_group;" ::: "memory");
}
template <int N>
__device__ __forceinline__ void cp_wait() {
    asm volatile("cp.async.wait_group %0;" :: "n"(N) : "memory");
}
__device__ __forceinline__ void ldsm4(uint32_t* r, uint32_t addr) {
    asm volatile("ldmatrix.sync.aligned.m8n8.x4.shared.b16 {%0,%1,%2,%3}, [%4];"
                 : "=r"(r[0]), "=r"(r[1]), "=r"(r[2]), "=r"(r[3]) : "r"(addr));
}
__device__ __forceinline__ void mma_bf16(float* c, const uint32_t* a, const uint32_t* b) {
    asm volatile(
        "mma.sync.aligned.m16n8k16.row.col.f32.bf16.bf16.f32 "
        "{%0,%1,%2,%3}, {%4,%5,%6,%7}, {%8,%9}, {%0,%1,%2,%3};"
        : "+f"(c[0]), "+f"(c[1]), "+f"(c[2]), "+f"(c[3])
        : "r"(a[0]), "r"(a[1]), "r"(a[2]), "r"(a[3]), "r"(b[0]), "r"(b[1]));
}
__device__ __forceinline__ uint32_t packbf(float lo_elem, float hi_elem) {
    uint32_t w;
    asm("cvt.rn.bf16x2.f32 %0, %1, %2;" : "=r"(w) : "f"(hi_elem), "f"(lo_elem));
    return w;
}

// ---------------------------------------------------------------------------
// Index-dtype detection (indexes may be int32 or int64; values < 2^23)
// ---------------------------------------------------------------------------
__global__ void zero_flag_kernel() { g_odd_or = 0u; }

__global__ void detect_kernel(const unsigned int* __restrict__ w, int n_words) {
    int i = blockIdx.x * blockDim.x + threadIdx.x;
    unsigned int v = 0u;
    for (int p = 2 * i + 1; p < n_words; p += 2 * gridDim.x * blockDim.x) v |= w[p];
    for (int o = 16; o; o >>= 1) v |= __shfl_down_sync(0xFFFFFFFFu, v, o);
    if ((threadIdx.x & 31) == 0 && v) atomicOr(&g_odd_or, v);
}

// ---------------------------------------------------------------------------
// Weight norm: W1 node-part -> bf16 hi, W1 q-part -> fp32, W2 -> bf16 hi
// ---------------------------------------------------------------------------
__global__ void wn_kernel(const float* __restrict__ v1, const float* __restrict__ g1,
                          const float* __restrict__ v2, const float* __restrict__ g2) {
    int r = blockIdx.x;
    const float* src;
    int len;
    float g;
    if (r < QD) { src = v1 + (size_t)r * CD; len = CD; g = g1[r]; }
    else        { src = v2 + (size_t)(r - QD) * QD; len = QD; g = g2[r - QD]; }

    float s = 0.f;
    for (int i = threadIdx.x; i < len; i += blockDim.x) { float x = src[i]; s += x * x; }

    __shared__ float red[32];
    for (int o = 16; o; o >>= 1) s += __shfl_down_sync(0xFFFFFFFFu, s, o);
    if ((threadIdx.x & 31) == 0) red[threadIdx.x >> 5] = s;
    __syncthreads();
    if (threadIdx.x < 32) {
        float t = (threadIdx.x < (blockDim.x >> 5)) ? red[threadIdx.x] : 0.f;
        for (int o = 16; o; o >>= 1) t += __shfl_down_sync(0xFFFFFFFFu, t, o);
        if (threadIdx.x == 0) red[0] = rsqrtf(t);
    }
    __syncthreads();
    float scale = g * red[0];

    if (r < QD) {
        for (int i = threadIdx.x; i < CD; i += blockDim.x) {
            float x = src[i] * scale;
            if (i < OBJ) g_W1hi[(size_t)r * OBJ + i] = __float2bfloat16(x);
            else         g_W1q[(size_t)r * QD + (i - OBJ)] = x;
        }
    } else {
        int rr = r - QD;
        for (int i = threadIdx.x; i < QD; i += blockDim.x)
            g_W2hi[(size_t)rr * QD + i] = __float2bfloat16(src[i] * scale);
    }
}

// ---------------------------------------------------------------------------
// node_feats fp32 -> bf16 hi/lo split
// ---------------------------------------------------------------------------
__global__ void node_cvt_kernel(const float* __restrict__ node) {
    size_t i4 = (size_t)blockIdx.x * blockDim.x + threadIdx.x;
    float4 v = *(const float4*)(node + i4 * 4);
    __nv_bfloat16 h0 = __float2bfloat16(v.x), h1 = __float2bfloat16(v.y);
    __nv_bfloat16 h2 = __float2bfloat16(v.z), h3 = __float2bfloat16(v.w);
    uint2 hw, lw;
    hw.x = packbf(__bfloat162float(h0), __bfloat162float(h1));
    hw.y = packbf(__bfloat162float(h2), __bfloat162float(h3));
    lw.x = packbf(v.x - __bfloat162float(h0), v.y - __bfloat162float(h1));
    lw.y = packbf(v.z - __bfloat162float(h2), v.w - __bfloat162float(h3));
    *(uint2*)(g_nhi + i4 * 4) = hw;
    *(uint2*)(g_nlo + i4 * 4) = lw;
}

// ---------------------------------------------------------------------------
// qterm[b, d] = b1[d] + sum_c q_feats[b, c] * W1q[d, c]
// ---------------------------------------------------------------------------
__global__ void qterm_kernel(const float* __restrict__ q_feats, const float* __restrict__ b1) {
    __shared__ __align__(16) float w[QD];
    int d = blockIdx.x;
    for (int i = threadIdx.x; i < QD; i += blockDim.x) w[i] = g_W1q[(size_t)d * QD + i];
    __syncthreads();
    int wid = threadIdx.x >> 5, lane = threadIdx.x & 31;
    float bias = b1[d];
    for (int b = wid; b < B_; b += 8) {
        const float* q = q_feats + (size_t)b * QD;
        float s = 0.f;
        for (int c = lane; c < QD; c += 32) s = fmaf(w[c], q[c], s);
        for (int o = 16; o; o >>= 1) s += __shfl_down_sync(0xFFFFFFFFu, s, o);
        if (lane == 0) g_qterm[(size_t)b * QD + d] = s + bias;
    }
}

// ---------------------------------------------------------------------------
// 2-term bf16 NT GEMM: C = (Ahi + Alo) @ Bhi^T  (fp32 accum)
// CTA tile 128(M) x 256(N), BK=32 per stage, 8 warps (2M x 4N), warp 64x64.
// 3-stage cp.async pipeline (120 KB smem), one sync per 128 MMAs.
// smem row stride 40 bf16 (80 B = 5x16B odd) -> conflict-free LDSM.
// MODE 1: A=node hi/lo, B=W1 hi (K=2048), epi relu(+qterm) -> h1 hi/lo
// MODE 2: A=h1 hi/lo,  B=W2 hi (K=1024), epi relu(+b2)    -> h2 hi/lo
// MODE 0: per-batch z: A=h2[z] hi/lo, B=h2[z] hi (K=1024), epi fp32 -> g_S
// ---------------------------------------------------------------------------
#define SROW      40
#define OFF_AHI   0
#define OFF_ALO   (128 * SROW)               // 5120 elems
#define OFF_BHI   (2 * 128 * SROW)           // 10240 elems
#define SSTAGE    (OFF_BHI + 256 * SROW)     // 20480 elems = 40960 B
#define NSTAGE    3
#define GEMM_SMEM (NSTAGE * SSTAGE * 2)      // 122880 B

template <int MODE>
__global__ void __launch_bounds__(256, 1) bf2_gemm(const float* __restrict__ bias) {
    constexpr int K   = (MODE == 1) ? OBJ : QD;
    constexpr int NIT = K / 32;
    constexpr size_t ldk = (MODE == 1) ? OBJ : QD;

    extern __shared__ __align__(16) __nv_bfloat16 dsm[];
    const uint32_t sb = smem_u32(dsm);

    const int tid  = threadIdx.x;
    const int wid  = tid >> 5;
    const int lane = tid & 31;
    const int wm   = wid >> 2;            // 0..1  (64 M-rows)
    const int wn   = wid & 3;             // 0..3  (64 N-cols)
    const int gr   = lane >> 2;           // 0..7
    const int ct   = lane & 3;            // 0..3
    const int m0   = blockIdx.y * 128;
    const int n0   = blockIdx.x * 256;

    const __nv_bfloat16 *Ahi, *Alo, *Bhi;
    if (MODE == 1)      { Ahi = g_nhi;  Alo = g_nlo;  Bhi = g_W1hi; }
    else if (MODE == 2) { Ahi = g_h1hi; Alo = g_h1lo; Bhi = g_W2hi; }
    else {
        size_t off = (size_t)blockIdx.z * ((size_t)N_ * QD);
        Ahi = g_h2hi + off; Alo = g_h2lo + off; Bhi = g_h2hi + off;
    }

    // loaders: A -> thread t: row t>>1, 16-elem chunk (t&1); B -> row t, 32 elems
    const int arow = tid >> 1;
    const int aq   = (tid & 1) * 16;                   // element offset within k32
    const __nv_bfloat16* gAh = Ahi + (size_t)(m0 + arow) * ldk + aq;
    const __nv_bfloat16* gAl = Alo + (size_t)(m0 + arow) * ldk + aq;
    const __nv_bfloat16* gB  = Bhi + (size_t)(n0 + tid) * ldk;
    const uint32_t dA  = (uint32_t)((OFF_AHI + arow * SROW + aq) * 2);
    const uint32_t dAl = (uint32_t)((OFF_ALO + arow * SROW + aq) * 2);
    const uint32_t dB  = (uint32_t)((OFF_BHI + tid * SROW) * 2);

    auto issue = [&](int it) {
        const uint32_t s0 = sb + (uint32_t)((it % NSTAGE) * SSTAGE * 2);
        const size_t k0 = (size_t)it * 32;
        cp16(s0 + dA,       gAh + k0);
        cp16(s0 + dA + 16,  gAh + k0 + 8);
        cp16(s0 + dAl,      gAl + k0);
        cp16(s0 + dAl + 16, gAl + k0 + 8);
        cp16(s0 + dB,       gB + k0);
        cp16(s0 + dB + 16,  gB + k0 + 8);
        cp16(s0 + dB + 32,  gB + k0 + 16);
        cp16(s0 + dB + 48,  gB + k0 + 24);
    };

    // ldmatrix byte offsets (relative to stage base, k-substep adds ks*32 B)
    const int lg = lane >> 3, lr = lane & 7;
    uint32_t aoffb[4], boffb[4];
#pragma unroll
    for (int mt = 0; mt < 4; mt++) {
        int row = wm * 64 + mt * 16 + (lg & 1) * 8 + lr;
        int q   = lg >> 1;
        aoffb[mt] = (uint32_t)((OFF_AHI + row * SROW + q * 8) * 2);
    }
#pragma unroll
    for (int p = 0; p < 4; p++) {
        int row = wn * 64 + (2 * p + (lg >> 1)) * 8 + lr;
        int q   = lg & 1;
        boffb[p] = (uint32_t)((OFF_BHI + row * SROW + q * 8) * 2);
    }
    const uint32_t lo_delta = (uint32_t)((OFF_ALO - OFF_AHI) * 2);

    float acc[4][8][4];
#pragma unroll
    for (int i = 0; i < 4; i++)
#pragma unroll
        for (int j = 0; j < 8; j++)
#pragma unroll
            for (int r = 0; r < 4; r++) acc[i][j][r] = 0.f;

    // prologue: 2 stages in flight
    issue(0); cp_commit();
    issue(1); cp_commit();

    for (int it = 0; it < NIT; ++it) {
        cp_wait<1>();
        __syncthreads();
        if (it + 2 < NIT) issue(it + 2);
        cp_commit();

        const uint32_t base = sb + (uint32_t)((it % NSTAGE) * SSTAGE * 2);
#pragma unroll
        for (int ks = 0; ks < 2; ks++) {
            const uint32_t kb = base + ks * 32;        // +16 elems per substep
            uint32_t ah[4][4], al[4][4], bt[4][4];
#pragma unroll
            for (int mt = 0; mt < 4; mt++) {
                ldsm4(ah[mt], kb + aoffb[mt]);
                ldsm4(al[mt], kb + aoffb[mt] + lo_delta);
            }
#pragma unroll
            for (int p = 0; p < 4; p++) ldsm4(bt[p], kb + boffb[p]);
#pragma unroll
            for (int p = 0; p < 4; p++)
#pragma unroll
                for (int mt = 0; mt < 4; mt++) {
                    mma_bf16(acc[mt][2 * p],     ah[mt], bt[p]);
                    mma_bf16(acc[mt][2 * p + 1], ah[mt], bt[p] + 2);
                }
#pragma unroll
            for (int p = 0; p < 4; p++)
#pragma unroll
                for (int mt = 0; mt < 4; mt++) {
                    mma_bf16(acc[mt][2 * p],     al[mt], bt[p]);
                    mma_bf16(acc[mt][2 * p + 1], al[mt], bt[p] + 2);
                }
        }
    }

    // ---- epilogue -----------------------------------------------------------
#pragma unroll
    for (int mt = 0; mt < 4; mt++) {
        int row_a = m0 + wm * 64 + mt * 16 + gr;
#pragma unroll
        for (int nt = 0; nt < 8; nt++) {
            int col = n0 + wn * 64 + nt * 8 + 2 * ct;
            float v0 = acc[mt][nt][0], v1 = acc[mt][nt][1];
            float v2 = acc[mt][nt][2], v3 = acc[mt][nt][3];
            if (MODE == 0) {
                float* dst = g_S + (size_t)blockIdx.z * ((size_t)N_ * N_);
                *(float2*)(dst + (size_t)row_a * N_ + col)       = make_float2(v0, v1);
                *(float2*)(dst + (size_t)(row_a + 8) * N_ + col) = make_float2(v2, v3);
            } else {
                const float* bsrc = (MODE == 1) ? (g_qterm + (size_t)(row_a >> 9) * QD) : bias;
                float b0 = bsrc[col], b1v = bsrc[col + 1];
                v0 = fmaxf(v0 + b0, 0.f);  v1 = fmaxf(v1 + b1v, 0.f);
                v2 = fmaxf(v2 + b0, 0.f);  v3 = fmaxf(v3 + b1v, 0.f);
                __nv_bfloat16* dh = (MODE == 1) ? g_h1hi : g_h2hi;
                __nv_bfloat16* dl = (MODE == 1) ? g_h1lo : g_h2lo;
                float h0 = __bfloat162float(__float2bfloat16(v0));
                float h1 = __bfloat162float(__float2bfloat16(v1));
                float h2 = __bfloat162float(__float2bfloat16(v2));
                float h3 = __bfloat162float(__float2bfloat16(v3));
                *(uint32_t*)(dh + (size_t)row_a * QD + col)       = packbf(h0, h1);
                *(uint32_t*)(dl + (size_t)row_a * QD + col)       = packbf(v0 - h0, v1 - h1);
                *(uint32_t*)(dh + (size_t)(row_a + 8) * QD + col) = packbf(h2, h3);
                *(uint32_t*)(dl + (size_t)(row_a + 8) * QD + col) = packbf(v2 - h2, v3 - h3);
            }
        }
    }
}

// ---------------------------------------------------------------------------
// Gather
// ---------------------------------------------------------------------------
__global__ void gather_kernel(const void* __restrict__ idx, float* __restrict__ out, int n) {
    int e = blockIdx.x * blockDim.x + threadIdx.x;
    if (e >= n) return;
    bool is64 = (g_odd_or == 0u);
    long long v = is64 ? ((const long long*)idx)[e] : (long long)((const int*)idx)[e];
    if (v < 0) v = 0;
    if (v >= (long long)STOT) v = (long long)STOT - 1;
    out[e] = g_S[v];
}

// ---------------------------------------------------------------------------
// Host entry (graph-capturable: kernel launches only)
// Launch order puts GEMM1 at slot 3 — the slot ncu's -s 5 -c 1 capture has
// been observed to land on — so the profile finally shows the GEMM.
// ---------------------------------------------------------------------------
extern "C" void kernel_launch(void* const* d_in, const int* in_sizes, int n_in,
                              void* d_out, int out_size) {
    const float* node = (const float*)d_in[0];
    const float* qf   = (const float*)d_in[1];
    const void*  idx  = d_in[2];
    const float* v1   = (const float*)d_in[3];
    const float* g1   = (const float*)d_in[4];
    const float* b1   = (const float*)d_in[5];
    const float* v2   = (const float*)d_in[6];
    const float* g2   = (const float*)d_in[7];
    const float* b2   = (const float*)d_in[8];
    float*       out  = (float*)d_out;

    (void)n_in; (void)in_sizes;

    static bool attr_done = false;
    if (!attr_done) {
        cudaFuncSetAttribute(bf2_gemm<1>, cudaFuncAttributeMaxDynamicSharedMemorySize, GEMM_SMEM);
        cudaFuncSetAttribute(bf2_gemm<2>, cudaFuncAttributeMaxDynamicSharedMemorySize, GEMM_SMEM);
        cudaFuncSetAttribute(bf2_gemm<0>, cudaFuncAttributeMaxDynamicSharedMemorySize, GEMM_SMEM);
        attr_done = true;
    }

    // slot 0..2: prep
    node_cvt_kernel<<<(MTOT * (OBJ / 4)) / 256, 256>>>(node);
    wn_kernel<<<2 * QD, 256>>>(v1, g1, v2, g2);
    qterm_kernel<<<QD, 256>>>(qf, b1);

    // slot 3: GEMM1  h1 = relu(node @ W1a^T + qterm)
    bf2_gemm<1><<<dim3(QD / 256, MTOT / 128), 256, GEMM_SMEM>>>(nullptr);
    // slot 4: GEMM2  h2 = relu(h1 @ W2^T + b2)
    bf2_gemm<2><<<dim3(QD / 256, MTOT / 128), 256, GEMM_SMEM>>>(b2);
    // slot 5: GEMM3  S[b] = h2[b] @ h2[b]^T
    bf2_gemm<0><<<dim3(N_ / 256, N_ / 128, B_), 256, GEMM_SMEM>>>(nullptr);

    // slot 6..8: index dtype detect + gather
    zero_flag_kernel<<<1, 1>>>();
    detect_kernel<<<128, 256>>>((const unsigned int*)idx, out_size);
    gather_kernel<<<(out_size + 255) / 256, 256>>>(idx, out, out_size);
}

// round 9
// speedup vs baseline: 1.8317x; 1.8317x over previous
#include <cuda_runtime.h>
#include <cuda_bf16.h>
#include <cstdint>

// ---------------------------------------------------------------------------
// Problem constants
// ---------------------------------------------------------------------------
#define B_    32
#define N_    512
#define OBJ   2048
#define QD    1024
#define CD    3072
#define MTOT  16384
#define STOT  ((size_t)B_ * N_ * N_)

// ---------------------------------------------------------------------------
// Device scratch (static; no runtime allocation)
// ---------------------------------------------------------------------------
__device__ __align__(16) __nv_bfloat16 g_W1hi[(size_t)QD * OBJ];
__device__ __align__(16) float         g_W1q [(size_t)QD * QD];
__device__ __align__(16) __nv_bfloat16 g_W2hi[(size_t)QD * QD];
__device__ __align__(16) __nv_bfloat16 g_nhi [(size_t)MTOT * OBJ];
__device__ __align__(16) __nv_bfloat16 g_h1hi[(size_t)MTOT * QD];
__device__ __align__(16) __nv_bfloat16 g_h2hi[(size_t)MTOT * QD];
__device__ __align__(16) float g_S[STOT];
__device__ __align__(16) float g_qterm[B_ * QD];
__device__ unsigned int g_odd_or;

// ---------------------------------------------------------------------------
// helpers
// ---------------------------------------------------------------------------
__device__ __forceinline__ uint32_t smem_u32(const void* p) {
    uint32_t a;
    asm("{ .reg .u64 t; cvta.to.shared.u64 t, %1; cvt.u32.u64 %0, t; }" : "=r"(a) : "l"(p));
    return a;
}
__device__ __forceinline__ void cp16(uint32_t dst, const void* src) {
    asm volatile("cp.async.ca.shared.global [%0], [%1], 16;" :: "r"(dst), "l"(src) : "memory");
}
__device__ __forceinline__ void cp_commit() {
    asm volatile("cp.async.commit_group;" ::: "memory");
}
template <int N>
__device__ __forceinline__ void cp_wait() {
    asm volatile("cp.async.wait_group %0;" :: "n"(N) : "memory");
}
__device__ __forceinline__ void ldsm4(uint32_t* r, uint32_t addr) {
    asm volatile("ldmatrix.sync.aligned.m8n8.x4.shared.b16 {%0,%1,%2,%3}, [%4];"
                 : "=r"(r[0]), "=r"(r[1]), "=r"(r[2]), "=r"(r[3]) : "r"(addr));
}
__device__ __forceinline__ void mma_bf16(float* c, const uint32_t* a, const uint32_t* b) {
    asm volatile(
        "mma.sync.aligned.m16n8k16.row.col.f32.bf16.bf16.f32 "
        "{%0,%1,%2,%3}, {%4,%5,%6,%7}, {%8,%9}, {%0,%1,%2,%3};"
        : "+f"(c[0]), "+f"(c[1]), "+f"(c[2]), "+f"(c[3])
        : "r"(a[0]), "r"(a[1]), "r"(a[2]), "r"(a[3]), "r"(b[0]), "r"(b[1]));
}
__device__ __forceinline__ uint32_t packbf(float lo_elem, float hi_elem) {
    uint32_t w;
    asm("cvt.rn.bf16x2.f32 %0, %1, %2;" : "=r"(w) : "f"(hi_elem), "f"(lo_elem));
    return w;
}

// ---------------------------------------------------------------------------
// Index-dtype detection (indexes may be int32 or int64; values < 2^23)
// ---------------------------------------------------------------------------
__global__ void zero_flag_kernel() { g_odd_or = 0u; }

__global__ void detect_kernel(const unsigned int* __restrict__ w, int n_words) {
    int i = blockIdx.x * blockDim.x + threadIdx.x;
    unsigned int v = 0u;
    for (int p = 2 * i + 1; p < n_words; p += 2 * gridDim.x * blockDim.x) v |= w[p];
    for (int o = 16; o; o >>= 1) v |= __shfl_down_sync(0xFFFFFFFFu, v, o);
    if ((threadIdx.x & 31) == 0 && v) atomicOr(&g_odd_or, v);
}

// ---------------------------------------------------------------------------
// Weight norm: W1 node-part -> bf16, W1 q-part -> fp32, W2 -> bf16
// ---------------------------------------------------------------------------
__global__ void wn_kernel(const float* __restrict__ v1, const float* __restrict__ g1,
                          const float* __restrict__ v2, const float* __restrict__ g2) {
    int r = blockIdx.x;
    const float* src;
    int len;
    float g;
    if (r < QD) { src = v1 + (size_t)r * CD; len = CD; g = g1[r]; }
    else        { src = v2 + (size_t)(r - QD) * QD; len = QD; g = g2[r - QD]; }

    float s = 0.f;
    for (int i = threadIdx.x; i < len; i += blockDim.x) { float x = src[i]; s += x * x; }

    __shared__ float red[32];
    for (int o = 16; o; o >>= 1) s += __shfl_down_sync(0xFFFFFFFFu, s, o);
    if ((threadIdx.x & 31) == 0) red[threadIdx.x >> 5] = s;
    __syncthreads();
    if (threadIdx.x < 32) {
        float t = (threadIdx.x < (blockDim.x >> 5)) ? red[threadIdx.x] : 0.f;
        for (int o = 16; o; o >>= 1) t += __shfl_down_sync(0xFFFFFFFFu, t, o);
        if (threadIdx.x == 0) red[0] = rsqrtf(t);
    }
    __syncthreads();
    float scale = g * red[0];

    if (r < QD) {
        for (int i = threadIdx.x; i < CD; i += blockDim.x) {
            float x = src[i] * scale;
            if (i < OBJ) g_W1hi[(size_t)r * OBJ + i] = __float2bfloat16(x);
            else         g_W1q[(size_t)r * QD + (i - OBJ)] = x;
        }
    } else {
        int rr = r - QD;
        for (int i = threadIdx.x; i < QD; i += blockDim.x)
            g_W2hi[(size_t)rr * QD + i] = __float2bfloat16(src[i] * scale);
    }
}

// ---------------------------------------------------------------------------
// node_feats fp32 -> bf16
// ---------------------------------------------------------------------------
__global__ void node_cvt_kernel(const float* __restrict__ node) {
    size_t i4 = (size_t)blockIdx.x * blockDim.x + threadIdx.x;
    float4 v = *(const float4*)(node + i4 * 4);
    uint2 hw;
    hw.x = packbf(v.x, v.y);
    hw.y = packbf(v.z, v.w);
    *(uint2*)(g_nhi + i4 * 4) = hw;
}

// ---------------------------------------------------------------------------
// qterm[b, d] = b1[d] + sum_c q_feats[b, c] * W1q[d, c]
// ---------------------------------------------------------------------------
__global__ void qterm_kernel(const float* __restrict__ q_feats, const float* __restrict__ b1) {
    __shared__ __align__(16) float w[QD];
    int d = blockIdx.x;
    for (int i = threadIdx.x; i < QD; i += blockDim.x) w[i] = g_W1q[(size_t)d * QD + i];
    __syncthreads();
    int wid = threadIdx.x >> 5, lane = threadIdx.x & 31;
    float bias = b1[d];
    for (int b = wid; b < B_; b += 8) {
        const float* q = q_feats + (size_t)b * QD;
        float s = 0.f;
        for (int c = lane; c < QD; c += 32) s = fmaf(w[c], q[c], s);
        for (int o = 16; o; o >>= 1) s += __shfl_down_sync(0xFFFFFFFFu, s, o);
        if (lane == 0) g_qterm[(size_t)b * QD + d] = s + bias;
    }
}

// ---------------------------------------------------------------------------
// bf16 NT GEMM: C[m,n] = sum_k A[m,k] * B[n,k]  (fp32 accum)
// CTA tile 128(M) x 128(N), BK=32/stage, 8 warps (2M x 4N), warp tile 64x32.
// 3-stage cp.async pipeline, 60 KB smem, __launch_bounds__(256,2) -> 2 CTA/SM.
// smem row stride 40 bf16 (80 B, odd x16B) -> conflict-free LDSM.
// MODE 1: A=node bf16, B=W1 bf16 (K=2048), epi relu(+qterm) -> h1 bf16
// MODE 2: A=h1 bf16,  B=W2 bf16 (K=1024), epi relu(+b2)    -> h2 bf16
// MODE 0: per-batch z: A=B=h2[z] bf16 (K=1024), epi fp32 -> g_S
// ---------------------------------------------------------------------------
#define SROW      40
#define OFF_A     0
#define OFF_B     (128 * SROW)               // 5120 elems
#define SSTAGE    (OFF_B + 128 * SROW)       // 10240 elems = 20480 B
#define NSTAGE    3
#define GEMM_SMEM (NSTAGE * SSTAGE * 2)      // 61440 B

template <int MODE>
__global__ void __launch_bounds__(256, 2) bf_gemm(const float* __restrict__ bias) {
    constexpr int K   = (MODE == 1) ? OBJ : QD;
    constexpr int NIT = K / 32;
    constexpr size_t ldk = (MODE == 1) ? OBJ : QD;

    extern __shared__ __align__(16) __nv_bfloat16 dsm[];
    const uint32_t sb = smem_u32(dsm);

    const int tid  = threadIdx.x;
    const int wid  = tid >> 5;
    const int lane = tid & 31;
    const int wm   = wid >> 2;            // 0..1  (64 M-rows)
    const int wn   = wid & 3;             // 0..3  (32 N-cols)
    const int gr   = lane >> 2;           // 0..7
    const int ct   = lane & 3;            // 0..3
    const int m0   = blockIdx.y * 128;
    const int n0   = blockIdx.x * 128;

    const __nv_bfloat16 *A, *Bm;
    if (MODE == 1)      { A = g_nhi;  Bm = g_W1hi; }
    else if (MODE == 2) { A = g_h1hi; Bm = g_W2hi; }
    else {
        size_t off = (size_t)blockIdx.z * ((size_t)N_ * QD);
        A = g_h2hi + off; Bm = A;
    }

    // loaders: thread t -> row t>>1, 16-elem chunk (t&1), for both A and B
    const int lrow = tid >> 1;
    const int lq   = (tid & 1) * 16;
    const __nv_bfloat16* gA = A  + (size_t)(m0 + lrow) * ldk + lq;
    const __nv_bfloat16* gB = Bm + (size_t)(n0 + lrow) * ldk + lq;
    const uint32_t dA = (uint32_t)((OFF_A + lrow * SROW + lq) * 2);
    const uint32_t dB = (uint32_t)((OFF_B + lrow * SROW + lq) * 2);

    auto issue = [&](int it) {
        const uint32_t s0 = sb + (uint32_t)((it % NSTAGE) * SSTAGE * 2);
        const size_t k0 = (size_t)it * 32;
        cp16(s0 + dA,      gA + k0);
        cp16(s0 + dA + 16, gA + k0 + 8);
        cp16(s0 + dB,      gB + k0);
        cp16(s0 + dB + 16, gB + k0 + 8);
    };

    // ldmatrix byte offsets (relative to stage base; k-substep adds ks*32 B)
    const int lg = lane >> 3, lr = lane & 7;
    uint32_t aoffb[4], boffb[2];
#pragma unroll
    for (int mt = 0; mt < 4; mt++) {
        int row = wm * 64 + mt * 16 + (lg & 1) * 8 + lr;
        int q   = lg >> 1;
        aoffb[mt] = (uint32_t)((OFF_A + row * SROW + q * 8) * 2);
    }
#pragma unroll
    for (int p = 0; p < 2; p++) {
        int row = wn * 32 + (2 * p + (lg >> 1)) * 8 + lr;
        int q   = lg & 1;
        boffb[p] = (uint32_t)((OFF_B + row * SROW + q * 8) * 2);
    }

    float acc[4][4][4];
#pragma unroll
    for (int i = 0; i < 4; i++)
#pragma unroll
        for (int j = 0; j < 4; j++)
#pragma unroll
            for (int r = 0; r < 4; r++) acc[i][j][r] = 0.f;

    issue(0); cp_commit();
    issue(1); cp_commit();

    for (int it = 0; it < NIT; ++it) {
        cp_wait<1>();
        __syncthreads();
        if (it + 2 < NIT) issue(it + 2);
        cp_commit();

        const uint32_t base = sb + (uint32_t)((it % NSTAGE) * SSTAGE * 2);
#pragma unroll
        for (int ks = 0; ks < 2; ks++) {
            const uint32_t kb = base + ks * 32;        // +16 elems per substep
            uint32_t ah[4][4], bt[2][4];
#pragma unroll
            for (int mt = 0; mt < 4; mt++) ldsm4(ah[mt], kb + aoffb[mt]);
#pragma unroll
            for (int p = 0; p < 2; p++)    ldsm4(bt[p], kb + boffb[p]);
#pragma unroll
            for (int p = 0; p < 2; p++)
#pragma unroll
                for (int mt = 0; mt < 4; mt++) {
                    mma_bf16(acc[mt][2 * p],     ah[mt], bt[p]);
                    mma_bf16(acc[mt][2 * p + 1], ah[mt], bt[p] + 2);
                }
        }
    }

    // ---- epilogue -----------------------------------------------------------
#pragma unroll
    for (int mt = 0; mt < 4; mt++) {
        int row_a = m0 + wm * 64 + mt * 16 + gr;
#pragma unroll
        for (int nt = 0; nt < 4; nt++) {
            int col = n0 + wn * 32 + nt * 8 + 2 * ct;
            float v0 = acc[mt][nt][0], v1 = acc[mt][nt][1];
            float v2 = acc[mt][nt][2], v3 = acc[mt][nt][3];
            if (MODE == 0) {
                float* dst = g_S + (size_t)blockIdx.z * ((size_t)N_ * N_);
                *(float2*)(dst + (size_t)row_a * N_ + col)       = make_float2(v0, v1);
                *(float2*)(dst + (size_t)(row_a + 8) * N_ + col) = make_float2(v2, v3);
            } else {
                const float* bsrc = (MODE == 1) ? (g_qterm + (size_t)(row_a >> 9) * QD) : bias;
                float b0 = bsrc[col], b1v = bsrc[col + 1];
                v0 = fmaxf(v0 + b0, 0.f);  v1 = fmaxf(v1 + b1v, 0.f);
                v2 = fmaxf(v2 + b0, 0.f);  v3 = fmaxf(v3 + b1v, 0.f);
                __nv_bfloat16* dh = (MODE == 1) ? g_h1hi : g_h2hi;
                *(uint32_t*)(dh + (size_t)row_a * QD + col)       = packbf(v0, v1);
                *(uint32_t*)(dh + (size_t)(row_a + 8) * QD + col) = packbf(v2, v3);
            }
        }
    }
}

// ---------------------------------------------------------------------------
// Gather
// ---------------------------------------------------------------------------
__global__ void gather_kernel(const void* __restrict__ idx, float* __restrict__ out, int n) {
    int e = blockIdx.x * blockDim.x + threadIdx.x;
    if (e >= n) return;
    bool is64 = (g_odd_or == 0u);
    long long v = is64 ? ((const long long*)idx)[e] : (long long)((const int*)idx)[e];
    if (v < 0) v = 0;
    if (v >= (long long)STOT) v = (long long)STOT - 1;
    out[e] = g_S[v];
}

// ---------------------------------------------------------------------------
// Host entry (graph-capturable: kernel launches only)
// ---------------------------------------------------------------------------
extern "C" void kernel_launch(void* const* d_in, const int* in_sizes, int n_in,
                              void* d_out, int out_size) {
    const float* node = (const float*)d_in[0];
    const float* qf   = (const float*)d_in[1];
    const void*  idx  = d_in[2];
    const float* v1   = (const float*)d_in[3];
    const float* g1   = (const float*)d_in[4];
    const float* b1   = (const float*)d_in[5];
    const float* v2   = (const float*)d_in[6];
    const float* g2   = (const float*)d_in[7];
    const float* b2   = (const float*)d_in[8];
    float*       out  = (float*)d_out;

    (void)n_in; (void)in_sizes;

    cudaFuncSetAttribute(bf_gemm<1>, cudaFuncAttributeMaxDynamicSharedMemorySize, GEMM_SMEM);
    cudaFuncSetAttribute(bf_gemm<2>, cudaFuncAttributeMaxDynamicSharedMemorySize, GEMM_SMEM);
    cudaFuncSetAttribute(bf_gemm<0>, cudaFuncAttributeMaxDynamicSharedMemorySize, GEMM_SMEM);

    // slot 0..2: prep
    node_cvt_kernel<<<(MTOT * (OBJ / 4)) / 256, 256>>>(node);
    wn_kernel<<<2 * QD, 256>>>(v1, g1, v2, g2);
    qterm_kernel<<<QD, 256>>>(qf, b1);

    // slot 3: GEMM1  h1 = relu(node @ W1a^T + qterm)   (profiled slot)
    bf_gemm<1><<<dim3(QD / 128, MTOT / 128), 256, GEMM_SMEM>>>(nullptr);
    // slot 4: GEMM2  h2 = relu(h1 @ W2^T + b2)
    bf_gemm<2><<<dim3(QD / 128, MTOT / 128), 256, GEMM_SMEM>>>(b2);
    // slot 5: GEMM3  S[b] = h2[b] @ h2[b]^T
    bf_gemm<0><<<dim3(N_ / 128, N_ / 128, B_), 256, GEMM_SMEM>>>(nullptr);

    // slot 6..8: index dtype detect + gather
    zero_flag_kernel<<<1, 1>>>();
    detect_kernel<<<128, 256>>>((const unsigned int*)idx, out_size);
    gather_kernel<<<(out_size + 255) / 256, 256>>>(idx, out, out_size);
}